// round 11
// baseline (speedup 1.0000x reference)
#include <cuda_runtime.h>
#include <cstdint>

// Closed-form normalization constants (double precision, truncated at use).
#define Y00f  0.28209479177387814f
#define N10f  0.48860251190291992f
#define N20f  0.63078313050504001f
#define C21f  (-1.09254843059207907f)
#define C22f  0.54627421529603953f
#define K20f  0.35355339059327379f
#define K21f  0.20412414523193152f
#define K30f  0.06415002990995843f
#define K31f  0.04536092116208279f
#define K32f  0.02028602047074832f

typedef unsigned long long u64;

__device__ u64 g_A[34];   // packed (lo==hi) coefficient + constant table

__device__ __forceinline__ u64 pk(float lo, float hi) {
    u64 r; asm("mov.b64 %0,{%1,%2};" : "=l"(r) : "f"(lo), "f"(hi)); return r;
}
__device__ __forceinline__ void upk(u64 v, float& lo, float& hi) {
    asm("mov.b64 {%0,%1},%2;" : "=f"(lo), "=f"(hi) : "l"(v));
}
__device__ __forceinline__ u64 f2mul(u64 a, u64 b) {
    u64 d; asm("mul.rn.f32x2 %0,%1,%2;" : "=l"(d) : "l"(a), "l"(b)); return d;
}
__device__ __forceinline__ u64 f2fma(u64 a, u64 b, u64 c) {
    u64 d; asm("fma.rn.f32x2 %0,%1,%2,%3;" : "=l"(d) : "l"(a), "l"(b), "l"(c)); return d;
}
__device__ __forceinline__ u64 f2add(u64 a, u64 b) {
    u64 d; asm("add.rn.f32x2 %0,%1,%2;" : "=l"(d) : "l"(a), "l"(b)); return d;
}

// One-warp setup: fold all norms/scalings; append polynomial constants.
__global__ void setup_coeffs_kernel(const float* __restrict__ coeffs) {
    if (threadIdx.x == 0) {
        float c[14];
#pragma unroll
        for (int k = 0; k < 14; k++) c[k] = coeffs[k];
        float b0  =  2.0f * Y00f * c[0];
        float b1  =  Y00f * K20f * c[1];
        float a2  =  N10f * K21f * c[3];
        float a3  = -N10f * K21f * c[4];
        float a4  = -N10f * K21f * c[2];
        float a6  =  N10f * K31f * c[7];
        float a7  = -N10f * K31f * c[8];
        float a8  = -N10f * K31f * c[6];
        float n2  =  N20f * K32f * c[11];
        float q12 =  (4.0f / 9.0f) * C21f * K32f * c[12];
        float q10 =  (4.0f / 9.0f) * C21f * K32f * c[10];
        float e13 =  (4.0f / 9.0f) * C22f * K32f * c[13];
        float e9  =  (8.0f / 9.0f) * C22f * K32f * c[9];
        float w9a = (2.0f / 3.0f) * n2 - e13;
        float cw  = -(2.0f / 9.0f) * n2 + e13;
        float b5  =  Y00f * K30f * c[5];

        float v[34];
        v[0] = b0;  v[1] = -b1;  v[2] = 2.0f * b1;
        v[3] = a2;  v[4] = a3;   v[5] = a4;
        v[6] = a6;  v[7] = a7;   v[8] = a8;
        v[9] = w9a; v[10] = cw;  v[11] = q12; v[12] = q10;
        v[13] = -2.0f * e13;     v[14] = e9;
        // L30 expanded: l30b = la*r^2 + lb*r + lc   (b5 folded)
        v[15] = (4.0f / 9.0f) * b5;  v[16] = -4.0f * b5;  v[17] = 6.0f * b5;
        // g3c = ga*r + gb
        v[18] = -4.0f / 9.0f;  v[19] = 8.0f / 3.0f;
        v[20] = 1.0f;                                  // ONE
        // sin(x) = x*(((s9 y + s7) y + s5) y + s3) y + 1), y = x^2
        v[21] = -1.0f / 6.0f;        v[22] = 1.0f / 120.0f;
        v[23] = -1.0f / 5040.0f;     v[24] = 1.0f / 362880.0f;
        // cos(x) = (((k8 y + k6) y + k4) y + k2) y + 1
        v[25] = -0.5f;               v[26] = 1.0f / 24.0f;
        v[27] = -1.0f / 720.0f;      v[28] = 1.0f / 40320.0f;
        // exp(-r/6) = ((((e5 r + e4) r + e3) r + e2) r + e1) r + 1
        v[29] = -1.0f / 6.0f;        v[30] = 1.0f / 72.0f;
        v[31] = -1.0f / 1296.0f;     v[32] = 1.0f / 31104.0f;
        v[33] = -1.0f / 933120.0f;
#pragma unroll
        for (int k = 0; k < 34; k++) g_A[k] = pk(v[k], v[k]);
    }
}

// Packed sin/cos for x in [0,1): y = x^2 precomputed.
__device__ __forceinline__ u64 psin(u64 x, u64 y, const u64* a) {
    u64 p = f2fma(a[24], y, a[23]);
    p = f2fma(p, y, a[22]);
    p = f2fma(p, y, a[21]);
    p = f2fma(p, y, a[20]);
    return f2mul(p, x);
}
__device__ __forceinline__ u64 pcos(u64 y, const u64* a) {
    u64 p = f2fma(a[28], y, a[27]);
    p = f2fma(p, y, a[26]);
    p = f2fma(p, y, a[25]);
    return f2fma(p, y, a[20]);
}
// Packed exp(-r/6) for r in [0,1).
__device__ __forceinline__ u64 pexp6(u64 r, const u64* a) {
    u64 p = f2fma(a[33], r, a[32]);
    p = f2fma(p, r, a[31]);
    p = f2fma(p, r, a[30]);
    p = f2fma(p, r, a[29]);
    return f2fma(p, r, a[20]);
}

// Fully packed evaluation of two points from packed (R, TH, PH).
__device__ __forceinline__ u64 eval_pair(u64 R, u64 TH, u64 PH, const u64* a) {
    // Transcendentals (all polynomial, all packed).
    u64 YT = f2mul(TH, TH);
    u64 ST = psin(TH, YT, a);
    u64 CT = pcos(YT, a);
    u64 YP = f2mul(PH, PH);
    u64 SP = psin(PH, YP, a);
    u64 CP = pcos(YP, a);
    u64 T  = pexp6(R, a);     // e^{-r/6}

    u64 T2 = f2mul(T, T), T3 = f2mul(T2, T), T6 = f2mul(T3, T3);
    u64 R2 = f2mul(R, R);
    u64 SPSP = f2mul(SP, SP), SPCP = f2mul(SP, CP);
    u64 CTCT = f2mul(CT, CT), ST2 = f2mul(ST, ST), CTST = f2mul(CT, ST);

    // n=2 block: B3 = r*(X1 + b1n) + b1d
    u64 X1 = f2fma(CT, a[3], f2mul(ST, f2fma(CP, a[4], f2mul(SP, a[5]))));
    u64 B3 = f2fma(R, f2add(X1, a[1]), a[2]);

    // n=3 l=0..1: P2 = l30b + r*g3c*X2
    u64 X2 = f2fma(CT, a[6], f2mul(ST, f2fma(CP, a[7], f2mul(SP, a[8]))));
    u64 L30B = f2fma(f2fma(a[15], R, a[16]), R, a[17]);
    u64 G3 = f2mul(R, f2fma(R, a[18], a[19]));
    u64 P2 = f2fma(G3, X2, L30B);

    // n=3 l=2 (4/9 scaling folded into coefficients):
    u64 Y = f2fma(CP, a[11], f2mul(SP, a[12]));
    u64 Z = f2fma(SPCP, a[14], f2mul(SPSP, a[13]));
    u64 W = f2fma(ST2, Z, f2fma(CTST, Y, f2fma(CTCT, a[9], a[10])));
    u64 B2 = f2fma(R2, W, P2);

    return f2fma(T6, a[0], f2fma(T3, B3, f2mul(T2, B2)));
}

__global__ __launch_bounds__(128)
void orbital_eval_kernel(const float* __restrict__ pos,
                         float* __restrict__ out,
                         int n4, int n) {
    int i = blockIdx.x * blockDim.x + threadIdx.x;

    // Load packed table upfront via 128-bit loads (R3 pattern: ptxas
    // rematerializes these as L1 broadcast hits, keeping regs low).
    u64 a[34];
    {
        const ulonglong2* Ap = reinterpret_cast<const ulonglong2*>(g_A);
#pragma unroll
        for (int k = 0; k < 17; k++) {
            ulonglong2 v = __ldg(&Ap[k]);
            a[2 * k]     = v.x;
            a[2 * k + 1] = v.y;
        }
    }

    if (i < n4) {
        const float4* p4 = reinterpret_cast<const float4*>(pos);
        float4 v0 = p4[3 * i + 0];
        float4 v1 = p4[3 * i + 1];
        float4 v2 = p4[3 * i + 2];
        // Points: (v0.x,v0.y,v0.z) (v0.w,v1.x,v1.y) (v1.z,v1.w,v2.x) (v2.y,v2.z,v2.w)
        u64 R01 = pk(v0.x, v0.w), TH01 = pk(v0.y, v1.x), PH01 = pk(v0.z, v1.y);
        u64 R23 = pk(v1.z, v2.y), TH23 = pk(v1.w, v2.z), PH23 = pk(v2.x, v2.w);

        u64 r01 = eval_pair(R01, TH01, PH01, a);
        u64 r23 = eval_pair(R23, TH23, PH23, a);

        float4 o;
        upk(r01, o.x, o.y);
        upk(r23, o.z, o.w);
        __stcs(reinterpret_cast<float4*>(out) + i, o);
    }

    // Scalar tail (n % 4 != 0).
    int tail = n - n4 * 4;
    if (i < tail) {
        int idx = n4 * 4 + i;
        float r = pos[3 * idx], th = pos[3 * idx + 1], ph = pos[3 * idx + 2];
        u64 rr = eval_pair(pk(r, r), pk(th, th), pk(ph, ph), a);
        float lo, hi; upk(rr, lo, hi);
        out[idx] = lo;
    }
}

extern "C" void kernel_launch(void* const* d_in, const int* in_sizes, int n_in,
                              void* d_out, int out_size) {
    const float* pos    = (const float*)d_in[0];   // (2048, 4096, 3) fp32
    const float* coeffs = (const float*)d_in[1];   // (14,) fp32
    float* out          = (float*)d_out;           // (2048, 4096) fp32

    int n  = out_size;
    int n4 = n / 4;

    setup_coeffs_kernel<<<1, 32>>>(coeffs);

    const int threads = 128;
    int groups = (n4 > 0) ? n4 : 1;
    int blocks = (groups + threads - 1) / threads;
    orbital_eval_kernel<<<blocks, threads>>>(pos, out, n4, n);
}

// round 12
// speedup vs baseline: 1.4723x; 1.4723x over previous
#include <cuda_runtime.h>

// Closed-form normalization constants.
#define Y00f  0.28209479177387814f    // 1/(2*sqrt(pi))
#define N10f  0.48860251190291992f    // sqrt(3/(4pi))
#define N20f  0.63078313050504001f    // sqrt(5/(4pi))
#define C21f  (-1.09254843059207907f) // -(1/2)*sqrt(15/pi)
#define C22f  0.54627421529603953f    // (1/4)*sqrt(15/pi)
#define K20f  0.35355339059327379f    // 1/(2*sqrt(2))
#define K21f  0.20412414523193152f    // 1/(2*sqrt(6))
#define K30f  0.06415002990995843f    // 1/(9*sqrt(3))
#define K31f  0.04536092116208279f    // sqrt(1/486)
#define K32f  0.02028602047074832f    // sqrt(8/19440)

typedef unsigned long long u64;

__device__ u64 g_A[14];   // pre-packed combined coefficients (lo==hi)

__device__ __forceinline__ u64 pk(float lo, float hi) {
    u64 r; asm("mov.b64 %0,{%1,%2};" : "=l"(r) : "f"(lo), "f"(hi)); return r;
}
__device__ __forceinline__ void upk(u64 v, float& lo, float& hi) {
    asm("mov.b64 {%0,%1},%2;" : "=f"(lo), "=f"(hi) : "l"(v));
}
__device__ __forceinline__ u64 f2mul(u64 a, u64 b) {
    u64 d; asm("mul.rn.f32x2 %0,%1,%2;" : "=l"(d) : "l"(a), "l"(b)); return d;
}
__device__ __forceinline__ u64 f2fma(u64 a, u64 b, u64 c) {
    u64 d; asm("fma.rn.f32x2 %0,%1,%2,%3;" : "=l"(d) : "l"(a), "l"(b), "l"(c)); return d;
}
__device__ __forceinline__ u64 f2add(u64 a, u64 b) {
    u64 d; asm("add.rn.f32x2 %0,%1,%2;" : "=l"(d) : "l"(a), "l"(b)); return d;
}

// One-warp setup: fold norms into coefficients, pack, store to global table.
__global__ void setup_coeffs_kernel(const float* __restrict__ coeffs) {
    if (threadIdx.x == 0) {
        float c[14];
#pragma unroll
        for (int k = 0; k < 14; k++) c[k] = coeffs[k];
        float ac[14];
        ac[0]  =  Y00f * 2.0f * c[0];
        ac[1]  =  Y00f * K20f * c[1];
        ac[2]  =  N10f * K21f * c[3];
        ac[3]  = -N10f * K21f * c[4];
        ac[4]  = -N10f * K21f * c[2];
        ac[5]  =  Y00f * K30f * c[5];
        ac[6]  =  N10f * K31f * c[7];
        ac[7]  = -N10f * K31f * c[8];
        ac[8]  = -N10f * K31f * c[6];
        ac[9]  =  N20f * K32f * c[11];
        ac[10] =  C21f * K32f * c[12];
        ac[11] =  C21f * K32f * c[10];
        ac[12] =  C22f * K32f * c[13];
        ac[13] =  C22f * K32f * c[9];
#pragma unroll
        for (int k = 0; k < 14; k++) g_A[k] = pk(ac[k], ac[k]);
    }
}

// Per-point scalar prep. exp(-r/6) for r in [0,1): degree-5 Horner with
// IMMEDIATE coefficients (scalar FFMA-imm, rt=1, zero register-table cost).
// Max truncation error ~3e-8 on [0,1).
struct Prep { float r, t, ct, st, cp, sp, rho, tmr, fmr, l30, nspsq, ct2t; };

__device__ __forceinline__ Prep prep(float r, float th, float ph) {
    Prep p;
    p.r = r;
    __sincosf(th, &p.st, &p.ct);
    __sincosf(ph, &p.sp, &p.cp);
    // e^{-r/6} via Taylor (immediates fold into FFMA-imm forms).
    {
        float e = fmaf(r, -1.0f / 933120.0f, 1.0f / 31104.0f);
        e = fmaf(e, r, -1.0f / 1296.0f);
        e = fmaf(e, r, 1.0f / 72.0f);
        e = fmaf(e, r, -1.0f / 6.0f);
        p.t = fmaf(e, r, 1.0f);
    }
    p.rho   = r * (2.0f / 3.0f);
    p.tmr   = 2.0f - r;
    p.fmr   = 4.0f - p.rho;
    p.l30   = fmaf(p.rho - 6.0f, p.rho, 6.0f); // rho^2 - 6 rho + 6
    p.nspsq = p.sp * (-p.sp);                  // -sin^2(phi)
    p.ct2t  = fmaf(p.ct * p.ct, 1.5f, -0.5f);  // (3cos^2-1)/2
    return p;
}

// Packed evaluation of two points; a[] table loads rematerialize as L1 hits.
__device__ __forceinline__ u64 eval_pair(const Prep& p0, const Prep& p1, const u64* a) {
    u64 R   = pk(p0.r,   p1.r),   T    = pk(p0.t,    p1.t);
    u64 CT  = pk(p0.ct,  p1.ct),  ST   = pk(p0.st,   p1.st);
    u64 CP  = pk(p0.cp,  p1.cp),  SP   = pk(p0.sp,   p1.sp);
    u64 RHO = pk(p0.rho, p1.rho), TMR  = pk(p0.tmr,  p1.tmr);
    u64 FMR = pk(p0.fmr, p1.fmr), L30  = pk(p0.l30,  p1.l30);
    u64 NSQ = pk(p0.nspsq, p1.nspsq), CT2T = pk(p0.ct2t, p1.ct2t);

    u64 T2 = f2mul(T, T), T3 = f2mul(T2, T), T6 = f2mul(T3, T3);
    u64 G3 = f2mul(FMR, RHO);           // (4-rho)*rho
    u64 Q  = f2mul(RHO, RHO);           // rho^2
    u64 C2P  = f2fma(CP, CP, NSQ);      // cos(2phi)
    u64 SPCP = f2mul(SP, CP);
    u64 S2P  = f2add(SPCP, SPCP);       // sin(2phi)
    u64 CTST = f2mul(CT, ST), ST2 = f2mul(ST, ST);

    // n=2 block (×t3)
    u64 X1 = f2fma(CP, a[3], f2mul(SP, a[4]));
    X1     = f2fma(CT, a[2], f2mul(ST, X1));
    u64 B3 = f2fma(TMR, a[1], f2mul(R, X1));

    // n=3, l=0..1 block (×t2)
    u64 X2 = f2fma(CP, a[7], f2mul(SP, a[8]));
    X2     = f2fma(CT, a[6], f2mul(ST, X2));
    u64 P2 = f2fma(L30, a[5], f2mul(G3, X2));

    // n=3, l=2 block
    u64 Y = f2fma(CP, a[10], f2mul(SP, a[11]));
    Y     = f2mul(CTST, Y);
    u64 Z = f2fma(C2P, a[12], f2mul(S2P, a[13]));
    u64 W = f2fma(ST2, Z, f2fma(CT2T, a[9], Y));
    u64 B2 = f2fma(Q, W, P2);

    return f2fma(T6, a[0], f2fma(T3, B3, f2mul(T2, B2)));
}

__global__ __launch_bounds__(256)
void orbital_eval_kernel(const float* __restrict__ pos,
                         float* __restrict__ out,
                         int n4, int n) {
    int i = blockIdx.x * blockDim.x + threadIdx.x;

    // Load pre-packed combined coefficients (7x 16B, L1-broadcast).
    u64 a[14];
    {
        const ulonglong2* Ap = reinterpret_cast<const ulonglong2*>(g_A);
#pragma unroll
        for (int k = 0; k < 7; k++) {
            ulonglong2 v = __ldg(&Ap[k]);
            a[2 * k]     = v.x;
            a[2 * k + 1] = v.y;
        }
    }

    if (i < n4) {
        const float4* p4 = reinterpret_cast<const float4*>(pos);
        float4 va = p4[3 * i + 0];
        float4 vb = p4[3 * i + 1];
        float4 vc = p4[3 * i + 2];
        float2* o2 = reinterpret_cast<float2*>(out);

        // Pair 0: (va.x,va.y,va.z), (va.w,vb.x,vb.y)
        {
            Prep q0 = prep(va.x, va.y, va.z);
            Prep q1 = prep(va.w, vb.x, vb.y);
            u64 r01 = eval_pair(q0, q1, a);
            float2 o; upk(r01, o.x, o.y);
            o2[2 * i] = o;
        }
        // Pair 1: (vb.z,vb.w,vc.x), (vc.y,vc.z,vc.w)
        {
            Prep q2 = prep(vb.z, vb.w, vc.x);
            Prep q3 = prep(vc.y, vc.z, vc.w);
            u64 r23 = eval_pair(q2, q3, a);
            float2 o; upk(r23, o.x, o.y);
            o2[2 * i + 1] = o;
        }
    }

    // Scalar tail (n % 4 != 0): duplicated pair, keep lo half.
    int tail = n - n4 * 4;
    if (i < tail) {
        int idx = n4 * 4 + i;
        Prep p = prep(pos[3 * idx], pos[3 * idx + 1], pos[3 * idx + 2]);
        u64 rr = eval_pair(p, p, a);
        float lo, hi; upk(rr, lo, hi);
        out[idx] = lo;
    }
}

extern "C" void kernel_launch(void* const* d_in, const int* in_sizes, int n_in,
                              void* d_out, int out_size) {
    const float* pos    = (const float*)d_in[0];   // (2048, 4096, 3) fp32
    const float* coeffs = (const float*)d_in[1];   // (14,) fp32
    float* out          = (float*)d_out;           // (2048, 4096) fp32

    int n  = out_size;
    int n4 = n / 4;

    setup_coeffs_kernel<<<1, 32>>>(coeffs);

    int threads = 256;
    int groups  = (n4 > 0) ? n4 : 1;
    int blocks  = (groups + threads - 1) / threads;
    orbital_eval_kernel<<<blocks, threads>>>(pos, out, n4, n);
}